// round 1
// baseline (speedup 1.0000x reference)
#include <cuda_runtime.h>
#include <math.h>
#include <stdint.h>

// ---------------- problem constants ----------------
#define B_    2
#define T_    2048
#define D_    1024
#define H_    16
#define DK_   64
#define DV_   128
#define NT    (B_*T_)       // 4096 tokens
#define KEY_DIM  1024
#define VAL_DIM  2048
#define INTER_   2752
#define CONV_    4

// ---------------- scratch (static device memory; no allocs allowed) ----------
constexpr size_t OFF_H    = 0;
constexpr size_t OFF_Q    = OFF_H    + (size_t)NT*D_;
constexpr size_t OFF_K    = OFF_Q    + (size_t)NT*KEY_DIM;
constexpr size_t OFF_V    = OFF_K    + (size_t)NT*KEY_DIM;
constexpr size_t OFF_QC   = OFF_V    + (size_t)NT*VAL_DIM;
constexpr size_t OFF_KC   = OFF_QC   + (size_t)NT*KEY_DIM;
constexpr size_t OFF_VC   = OFF_KC   + (size_t)NT*KEY_DIM;
constexpr size_t OFF_GATE = OFF_VC   + (size_t)NT*VAL_DIM;
constexpr size_t OFF_BETA = OFF_GATE + (size_t)NT*VAL_DIM;
constexpr size_t OFF_G    = OFF_BETA + (size_t)NT*H_;
constexpr size_t OFF_O    = OFF_G    + (size_t)NT*H_;
constexpr size_t OFF_XMID = OFF_O    + (size_t)NT*VAL_DIM;
constexpr size_t OFF_H2   = OFF_XMID + (size_t)NT*D_;
constexpr size_t OFF_MG   = OFF_H2   + (size_t)NT*D_;
constexpr size_t OFF_MU   = OFF_MG   + (size_t)NT*INTER_;
constexpr size_t SCR_TOTAL= OFF_MU   + (size_t)NT*INTER_;

__device__ float SCR[SCR_TOTAL];

// ---------------- helpers ----------------
__device__ __forceinline__ float sigmoidf_(float x){ return 1.0f/(1.0f+expf(-x)); }
__device__ __forceinline__ float siluf_(float x){ return x*sigmoidf_(x); }

// ---------------- rmsnorm over D=1024, one block per row ----------------
__global__ void rmsnorm_k(const float* __restrict__ x, const float* __restrict__ w,
                          float* __restrict__ out)
{
    int row = blockIdx.x;
    const float* xr = x + (size_t)row * D_;
    float*       orow = out + (size_t)row * D_;
    int tid = threadIdx.x;
    float v[4];
    float ss = 0.f;
#pragma unroll
    for (int i = 0; i < 4; i++) { v[i] = xr[tid + i*256]; ss += v[i]*v[i]; }
#pragma unroll
    for (int off = 16; off; off >>= 1) ss += __shfl_xor_sync(0xffffffffu, ss, off);
    __shared__ float red[8];
    int wid = tid >> 5, lane = tid & 31;
    if (lane == 0) red[wid] = ss;
    __syncthreads();
    if (wid == 0) {
        float t = (lane < 8) ? red[lane] : 0.f;
#pragma unroll
        for (int off = 4; off; off >>= 1) t += __shfl_xor_sync(0xffffffffu, t, off);
        if (lane == 0) red[0] = t;
    }
    __syncthreads();
    float scale = rsqrtf(red[0] * (1.0f/(float)D_) + 1e-6f);
#pragma unroll
    for (int i = 0; i < 4; i++) orow[tid + i*256] = v[i]*scale*w[tid + i*256];
}

// ---------------- generic tiled SGEMM: C = A[M,K] @ B[K,N] (+ Res) ----------
// 128x128 tile, BK=16, 8x8 per thread, 256 threads. M,K multiples of 16/128; N guarded.
__global__ __launch_bounds__(256, 2)
void sgemm_k(const float* __restrict__ A, const float* __restrict__ Bm,
             const float* __restrict__ Res, float* __restrict__ C,
             int M, int N, int K)
{
    const int BM=128, BN=128, BK=16;
    __shared__ float As[BM][BK+1];
    __shared__ float Bs[BK][BN];
    int tid = threadIdx.x;
    int tx = tid & 15, ty = tid >> 4;
    int rowBase = blockIdx.y * BM;
    int colBase = blockIdx.x * BN;

    float acc[8][8];
#pragma unroll
    for (int i=0;i<8;i++)
#pragma unroll
        for (int j=0;j<8;j++) acc[i][j]=0.f;

    for (int k0 = 0; k0 < K; k0 += BK) {
        // load A tile [BM x BK] (coalesced-ish: 16 consecutive threads per row)
#pragma unroll
        for (int i = tid; i < BM*BK; i += 256) {
            int m = i >> 4, kk = i & 15;
            As[m][kk] = A[(size_t)(rowBase+m)*K + k0 + kk];
        }
        // load B tile [BK x BN] (fully coalesced), guard N
#pragma unroll
        for (int i = tid; i < BK*BN; i += 256) {
            int kk = i >> 7, n = i & 127;
            int col = colBase + n;
            Bs[kk][n] = (col < N) ? Bm[(size_t)(k0+kk)*N + col] : 0.f;
        }
        __syncthreads();
#pragma unroll
        for (int kk = 0; kk < BK; kk++) {
            float a_[8];
#pragma unroll
            for (int i=0;i<8;i++) a_[i] = As[ty*8+i][kk];
            float4 b0 = *(const float4*)&Bs[kk][tx*8];
            float4 b1 = *(const float4*)&Bs[kk][tx*8+4];
            float b_[8] = {b0.x,b0.y,b0.z,b0.w,b1.x,b1.y,b1.z,b1.w};
#pragma unroll
            for (int i=0;i<8;i++)
#pragma unroll
                for (int j=0;j<8;j++) acc[i][j] = fmaf(a_[i], b_[j], acc[i][j]);
        }
        __syncthreads();
    }
    // epilogue
#pragma unroll
    for (int i=0;i<8;i++) {
        int row = rowBase + ty*8 + i;
#pragma unroll
        for (int j=0;j<8;j++) {
            int col = colBase + tx*8 + j;
            if (col < N) {
                size_t idx = (size_t)row*N + col;
                float r = Res ? Res[idx] : 0.f;
                C[idx] = acc[i][j] + r;
            }
        }
    }
}

// ---------------- causal depthwise conv (K=4) + SiLU ----------------
__global__ void conv_silu_k(const float* __restrict__ in, const float* __restrict__ w,
                            float* __restrict__ out, int C)
{
    size_t total = (size_t)NT * C;
    for (size_t idx = (size_t)blockIdx.x*blockDim.x + threadIdx.x; idx < total;
         idx += (size_t)gridDim.x*blockDim.x) {
        int c = (int)(idx % C);
        size_t bt = idx / C;
        int t = (int)(bt % T_);
        int b = (int)(bt / T_);
        float accv = 0.f;
#pragma unroll
        for (int j = 0; j < CONV_; j++) {
            int tt = t - (CONV_-1) + j;
            if (tt >= 0) accv = fmaf(in[((size_t)b*T_ + tt)*C + c], w[c*CONV_ + j], accv);
        }
        out[idx] = siluf_(accv);
    }
}

// ---------------- l2norm over last dim 64, one warp per (b,t,h) row --------
__global__ void l2norm_k(float* __restrict__ p, int nrows)
{
    int warp = (blockIdx.x * blockDim.x + threadIdx.x) >> 5;
    int lane = threadIdx.x & 31;
    if (warp >= nrows) return;
    float* base = p + (size_t)warp * 64;
    float a = base[lane], b = base[lane+32];
    float ss = a*a + b*b;
#pragma unroll
    for (int off = 16; off; off >>= 1) ss += __shfl_xor_sync(0xffffffffu, ss, off);
    float r = rsqrtf(ss + 1e-6f);
    base[lane] = a*r; base[lane+32] = b*r;
}

// ---------------- beta = sigmoid(hb), g = -exp(A_log)*softplus(ha+dt_bias) --
__global__ void beta_g_k(float* __restrict__ hb, float* __restrict__ ha,
                         const float* __restrict__ dt_bias, const float* __restrict__ A_log)
{
    int i = blockIdx.x*blockDim.x + threadIdx.x;
    if (i >= NT*H_) return;
    int h = i & (H_-1);
    hb[i] = sigmoidf_(hb[i]);
    float x = ha[i] + dt_bias[h];
    float sp = (x > 20.f) ? x : log1pf(expf(x));
    ha[i] = -expf(A_log[h]) * sp;
}

// ---------------- gated delta-rule scan: one CTA per (b,h), 128 threads ----
// Thread tid owns state column S[k=0..63][v=tid].
__global__ __launch_bounds__(128, 1)
void scan_k(const float* __restrict__ qn, const float* __restrict__ kn,
            const float* __restrict__ v,  const float* __restrict__ g,
            const float* __restrict__ beta, float* __restrict__ o)
{
    int b = blockIdx.x / H_;
    int h = blockIdx.x % H_;
    int tid = threadIdx.x;

    const float* qb = qn + (size_t)b*T_*KEY_DIM + h*DK_;
    const float* kb = kn + (size_t)b*T_*KEY_DIM + h*DK_;
    const float* vb = v  + (size_t)b*T_*VAL_DIM + h*DV_;
    const float* gb = g  + (size_t)b*T_*H_ + h;
    const float* bb = beta + (size_t)b*T_*H_ + h;
    float*       ob = o  + (size_t)b*T_*VAL_DIM + h*DV_;

    __shared__ float sk[DK_], sq[DK_], sv[DV_];
    __shared__ float s_scal[2];   // [0]=exp(g), [1]=beta

    float S[DK_];
#pragma unroll
    for (int j = 0; j < DK_; j++) S[j] = 0.f;

    // prefetch t=0
    float rk = 0.f, rq = 0.f, rv, rg = 0.f, rb = 0.f;
    if (tid < DK_) { rk = kb[tid]; rq = qb[tid]; }
    rv = vb[tid];
    if (tid == 0) { rg = gb[0]; rb = bb[0]; }

    for (int t = 0; t < T_; t++) {
        if (tid < DK_) { sk[tid] = rk; sq[tid] = rq; }
        sv[tid] = rv;
        if (tid == 0) { s_scal[0] = expf(rg); s_scal[1] = rb; }
        __syncthreads();

        // prefetch t+1 (overlaps compute; long-scoreboard hidden)
        if (t + 1 < T_) {
            size_t qk_off = (size_t)(t+1)*KEY_DIM;
            if (tid < DK_) { rk = kb[qk_off + tid]; rq = qb[qk_off + tid]; }
            rv = vb[(size_t)(t+1)*VAL_DIM + tid];
            if (tid == 0) { rg = gb[(size_t)(t+1)*H_]; rb = bb[(size_t)(t+1)*H_]; }
        }

        float decay = s_scal[0];
        float bt    = s_scal[1];
        float kv = 0.f;
#pragma unroll
        for (int j = 0; j < DK_; j++) kv = fmaf(sk[j], S[j], kv);
        kv *= decay;
        float u = bt * (sv[tid] - kv);
        float oacc = 0.f;
#pragma unroll
        for (int j = 0; j < DK_; j++) {
            float s = fmaf(sk[j], u, S[j]*decay);
            S[j] = s;
            oacc = fmaf(sq[j], s, oacc);
        }
        ob[(size_t)t*VAL_DIM + tid] = oacc * 0.125f;   // scale = 64^-0.5
        __syncthreads();
    }
}

// ---------------- o = rmsnorm(o, w)*silu(gate), one warp per (b,t,h) row ----
__global__ void onorm_gate_k(float* __restrict__ o, const float* __restrict__ gate,
                             const float* __restrict__ w, int nrows)
{
    int warp = (blockIdx.x * blockDim.x + threadIdx.x) >> 5;
    int lane = threadIdx.x & 31;
    if (warp >= nrows) return;
    float* ob = o + (size_t)warp * DV_;
    const float* gb = gate + (size_t)warp * DV_;
    float x[4];
    float ss = 0.f;
#pragma unroll
    for (int i = 0; i < 4; i++) { x[i] = ob[lane + i*32]; ss += x[i]*x[i]; }
#pragma unroll
    for (int off = 16; off; off >>= 1) ss += __shfl_xor_sync(0xffffffffu, ss, off);
    float scale = rsqrtf(ss * (1.0f/(float)DV_) + 1e-6f);
#pragma unroll
    for (int i = 0; i < 4; i++) {
        int d = lane + i*32;
        ob[d] = x[i]*scale*w[d] * siluf_(gb[d]);
    }
}

// ---------------- SwiGLU activation: mg = silu(mg)*mu ----------------
__global__ void act_mul_k(float* __restrict__ mg, const float* __restrict__ mu)
{
    size_t total = (size_t)NT * INTER_;
    for (size_t i = (size_t)blockIdx.x*blockDim.x + threadIdx.x; i < total;
         i += (size_t)gridDim.x*blockDim.x)
        mg[i] = siluf_(mg[i]) * mu[i];
}

// ---------------- launch ----------------
static inline dim3 gemm_grid(int M, int N) { return dim3((N+127)/128, (M+127)/128); }

extern "C" void kernel_launch(void* const* d_in, const int* in_sizes, int n_in,
                              void* d_out, int out_size)
{
    const float* x       = (const float*)d_in[0];
    const float* norm1_w = (const float*)d_in[1];
    const float* Wq      = (const float*)d_in[2];
    const float* Wk      = (const float*)d_in[3];
    const float* Wv      = (const float*)d_in[4];
    const float* Wb      = (const float*)d_in[5];
    const float* Wa      = (const float*)d_in[6];
    const float* Wg      = (const float*)d_in[7];
    const float* Wo      = (const float*)d_in[8];
    const float* conv_q  = (const float*)d_in[9];
    const float* conv_k  = (const float*)d_in[10];
    const float* conv_v  = (const float*)d_in[11];
    const float* dt_bias = (const float*)d_in[12];
    const float* A_log   = (const float*)d_in[13];
    const float* o_norm_w= (const float*)d_in[14];
    const float* norm2_w = (const float*)d_in[15];
    const float* Wgate   = (const float*)d_in[16];
    const float* Wup     = (const float*)d_in[17];
    const float* Wdown   = (const float*)d_in[18];
    float* out = (float*)d_out;

    float* scr = nullptr;
    cudaGetSymbolAddress((void**)&scr, SCR);
    float* Hbuf = scr + OFF_H;
    float* Q    = scr + OFF_Q;
    float* K    = scr + OFF_K;
    float* V    = scr + OFF_V;
    float* QC   = scr + OFF_QC;
    float* KC   = scr + OFF_KC;
    float* VC   = scr + OFF_VC;
    float* GATE = scr + OFF_GATE;
    float* BETA = scr + OFF_BETA;
    float* G    = scr + OFF_G;
    float* O    = scr + OFF_O;
    float* XMID = scr + OFF_XMID;
    float* H2   = scr + OFF_H2;
    float* MG   = scr + OFF_MG;
    float* MU   = scr + OFF_MU;

    // 1) pre-norm
    rmsnorm_k<<<NT, 256>>>(x, norm1_w, Hbuf);

    // 2) projections
    sgemm_k<<<gemm_grid(NT, KEY_DIM), 256>>>(Hbuf, Wq, nullptr, Q, NT, KEY_DIM, D_);
    sgemm_k<<<gemm_grid(NT, KEY_DIM), 256>>>(Hbuf, Wk, nullptr, K, NT, KEY_DIM, D_);
    sgemm_k<<<gemm_grid(NT, VAL_DIM), 256>>>(Hbuf, Wv, nullptr, V, NT, VAL_DIM, D_);
    sgemm_k<<<gemm_grid(NT, H_),      256>>>(Hbuf, Wb, nullptr, BETA, NT, H_, D_);
    sgemm_k<<<gemm_grid(NT, H_),      256>>>(Hbuf, Wa, nullptr, G, NT, H_, D_);
    sgemm_k<<<gemm_grid(NT, VAL_DIM), 256>>>(Hbuf, Wg, nullptr, GATE, NT, VAL_DIM, D_);

    // 3) conv + silu
    conv_silu_k<<<4096, 256>>>(Q, conv_q, QC, KEY_DIM);
    conv_silu_k<<<4096, 256>>>(K, conv_k, KC, KEY_DIM);
    conv_silu_k<<<8192, 256>>>(V, conv_v, VC, VAL_DIM);

    // 4) l2norm q,k (in-place)
    l2norm_k<<<(NT*H_ + 7)/8, 256>>>(QC, NT*H_);
    l2norm_k<<<(NT*H_ + 7)/8, 256>>>(KC, NT*H_);

    // 5) beta / g (in-place on BETA, G)
    beta_g_k<<<(NT*H_ + 255)/256, 256>>>(BETA, G, dt_bias, A_log);

    // 6) sequential gated delta-rule scan
    scan_k<<<B_*H_, 128>>>(QC, KC, VC, G, BETA, O);

    // 7) gated output norm (in-place on O)
    onorm_gate_k<<<(NT*H_ + 7)/8, 256>>>(O, GATE, o_norm_w, NT*H_);

    // 8) output projection + residual
    sgemm_k<<<gemm_grid(NT, D_), 256>>>(O, Wo, x, XMID, NT, D_, VAL_DIM);

    // 9) MLP
    rmsnorm_k<<<NT, 256>>>(XMID, norm2_w, H2);
    sgemm_k<<<gemm_grid(NT, INTER_), 256>>>(H2, Wgate, nullptr, MG, NT, INTER_, D_);
    sgemm_k<<<gemm_grid(NT, INTER_), 256>>>(H2, Wup,   nullptr, MU, NT, INTER_, D_);
    act_mul_k<<<8192, 256>>>(MG, MU);
    sgemm_k<<<gemm_grid(NT, D_), 256>>>(MG, Wdown, XMID, out, NT, D_, INTER_);
}

// round 2
// speedup vs baseline: 2.0646x; 2.0646x over previous
#include <cuda_runtime.h>
#include <math.h>
#include <stdint.h>

// ---------------- problem constants ----------------
#define B_    2
#define T_    2048
#define D_    1024
#define H_    16
#define DK_   64
#define DV_   128
#define NT    (B_*T_)       // 4096 tokens
#define KEY_DIM  1024
#define VAL_DIM  2048
#define INTER_   2752
#define CONV_    4

// ---------------- scratch (static device memory; no allocs allowed) ----------
constexpr size_t OFF_H    = 0;
constexpr size_t OFF_Q    = OFF_H    + (size_t)NT*D_;
constexpr size_t OFF_K    = OFF_Q    + (size_t)NT*KEY_DIM;
constexpr size_t OFF_V    = OFF_K    + (size_t)NT*KEY_DIM;
constexpr size_t OFF_QC   = OFF_V    + (size_t)NT*VAL_DIM;
constexpr size_t OFF_KC   = OFF_QC   + (size_t)NT*KEY_DIM;
constexpr size_t OFF_VC   = OFF_KC   + (size_t)NT*KEY_DIM;
constexpr size_t OFF_GATE = OFF_VC   + (size_t)NT*VAL_DIM;
constexpr size_t OFF_BETA = OFF_GATE + (size_t)NT*VAL_DIM;
constexpr size_t OFF_G    = OFF_BETA + (size_t)NT*H_;
constexpr size_t OFF_O    = OFF_G    + (size_t)NT*H_;
constexpr size_t OFF_XMID = OFF_O    + (size_t)NT*VAL_DIM;
constexpr size_t OFF_H2   = OFF_XMID + (size_t)NT*D_;
constexpr size_t OFF_MG   = OFF_H2   + (size_t)NT*D_;
constexpr size_t OFF_MU   = OFF_MG   + (size_t)NT*INTER_;
constexpr size_t SCR_TOTAL= OFF_MU   + (size_t)NT*INTER_;

__device__ float SCR[SCR_TOTAL];

// ---------------- helpers ----------------
__device__ __forceinline__ float sigmoidf_(float x){ return 1.0f/(1.0f+expf(-x)); }
__device__ __forceinline__ float siluf_(float x){ return x*sigmoidf_(x); }
__device__ __forceinline__ uint32_t f2tf32(float f){
    uint32_t u;
    asm("cvt.rna.tf32.f32 %0, %1;" : "=r"(u) : "f"(f));
    return u;
}
__device__ __forceinline__ void mma_tf32(float c[4], const uint32_t a[4], const uint32_t b[2]){
    asm volatile(
        "mma.sync.aligned.m16n8k8.row.col.f32.tf32.tf32.f32 "
        "{%0,%1,%2,%3}, {%4,%5,%6,%7}, {%8,%9}, {%0,%1,%2,%3};"
        : "+f"(c[0]), "+f"(c[1]), "+f"(c[2]), "+f"(c[3])
        : "r"(a[0]), "r"(a[1]), "r"(a[2]), "r"(a[3]), "r"(b[0]), "r"(b[1]));
}

// ---------------- rmsnorm over D=1024, one block per row ----------------
__global__ void rmsnorm_k(const float* __restrict__ x, const float* __restrict__ w,
                          float* __restrict__ out)
{
    int row = blockIdx.x;
    const float* xr = x + (size_t)row * D_;
    float*       orow = out + (size_t)row * D_;
    int tid = threadIdx.x;
    float v[4];
    float ss = 0.f;
#pragma unroll
    for (int i = 0; i < 4; i++) { v[i] = xr[tid + i*256]; ss += v[i]*v[i]; }
#pragma unroll
    for (int off = 16; off; off >>= 1) ss += __shfl_xor_sync(0xffffffffu, ss, off);
    __shared__ float red[8];
    int wid = tid >> 5, lane = tid & 31;
    if (lane == 0) red[wid] = ss;
    __syncthreads();
    if (wid == 0) {
        float t = (lane < 8) ? red[lane] : 0.f;
#pragma unroll
        for (int off = 4; off; off >>= 1) t += __shfl_xor_sync(0xffffffffu, t, off);
        if (lane == 0) red[0] = t;
    }
    __syncthreads();
    float scale = rsqrtf(red[0] * (1.0f/(float)D_) + 1e-6f);
#pragma unroll
    for (int i = 0; i < 4; i++) orow[tid + i*256] = v[i]*scale*w[tid + i*256];
}

// ---------------- TF32 tensor-core GEMM: C = A[M,K] @ B[K,N] (+ Res) -------
// 128x128x32 tile, 256 threads = 8 warps, warp tile 32x64 (2x8 m16n8k8 tiles
// per k-step). M multiple of 128, K multiple of 32, N multiple of 64 (tile-
// level N guard). Conflict-free shared layouts: A pitch 36, B pitch 136.
__global__ __launch_bounds__(256)
void mma_gemm_k(const float* __restrict__ A, const float* __restrict__ Bm,
                const float* __restrict__ Res, float* __restrict__ C,
                int M, int N, int K)
{
    __shared__ uint32_t As[128][36];
    __shared__ uint32_t Bs[32][136];
    int tid = threadIdx.x;
    int lane = tid & 31, warp = tid >> 5;
    int warpM = (warp & 3) * 32;
    int warpN = (warp >> 2) * 64;
    int rowBase = blockIdx.y * 128;
    int colBase = blockIdx.x * 128;
    int g = lane >> 2, tg = lane & 3;   // groupID / thread-in-group

    float acc[2][8][4];
#pragma unroll
    for (int mi=0;mi<2;mi++)
#pragma unroll
        for (int ni=0;ni<8;ni++)
#pragma unroll
            for (int j=0;j<4;j++) acc[mi][ni][j] = 0.f;

    // per-thread global->shared mapping (4 float4 each for A and B)
    int aRow[4], aCol[4], bRow[4], bCol[4];
#pragma unroll
    for (int p = 0; p < 4; p++) {
        int i = tid + p*256;
        aRow[p] = i >> 3;          aCol[p] = (i & 7) * 4;    // A: 128 rows x 32 cols
        bRow[p] = i >> 5;          bCol[p] = (i & 31) * 4;   // B: 32 rows x 128 cols
    }

    float4 pa[4], pb[4];
    // prefetch k0 = 0
#pragma unroll
    for (int p = 0; p < 4; p++)
        pa[p] = *(const float4*)&A[(size_t)(rowBase + aRow[p])*K + aCol[p]];
#pragma unroll
    for (int p = 0; p < 4; p++) {
        int col = colBase + bCol[p];
        pb[p] = (col < N) ? *(const float4*)&Bm[(size_t)bRow[p]*N + col]
                          : make_float4(0.f,0.f,0.f,0.f);
    }

    for (int k0 = 0; k0 < K; k0 += 32) {
        // commit prefetched regs to shared (with tf32 RN conversion)
#pragma unroll
        for (int p = 0; p < 4; p++) {
            uint4 u = { f2tf32(pa[p].x), f2tf32(pa[p].y), f2tf32(pa[p].z), f2tf32(pa[p].w) };
            *(uint4*)&As[aRow[p]][aCol[p]] = u;
        }
#pragma unroll
        for (int p = 0; p < 4; p++) {
            uint4 u = { f2tf32(pb[p].x), f2tf32(pb[p].y), f2tf32(pb[p].z), f2tf32(pb[p].w) };
            *(uint4*)&Bs[bRow[p]][bCol[p]] = u;
        }
        __syncthreads();

        // prefetch next k-tile (LDG overlapped with mma)
        if (k0 + 32 < K) {
            int kn = k0 + 32;
#pragma unroll
            for (int p = 0; p < 4; p++)
                pa[p] = *(const float4*)&A[(size_t)(rowBase + aRow[p])*K + kn + aCol[p]];
#pragma unroll
            for (int p = 0; p < 4; p++) {
                int col = colBase + bCol[p];
                pb[p] = (col < N) ? *(const float4*)&Bm[(size_t)(kn + bRow[p])*N + col]
                                  : make_float4(0.f,0.f,0.f,0.f);
            }
        }

        // compute: 4 k-steps of m16n8k8
#pragma unroll
        for (int kk = 0; kk < 4; kk++) {
            uint32_t af[2][4];
#pragma unroll
            for (int mi = 0; mi < 2; mi++) {
                int r = warpM + mi*16 + g;
                int c = kk*8 + tg;
                af[mi][0] = As[r][c];
                af[mi][1] = As[r+8][c];
                af[mi][2] = As[r][c+4];
                af[mi][3] = As[r+8][c+4];
            }
#pragma unroll
            for (int ni = 0; ni < 8; ni++) {
                uint32_t bf[2];
                int rr = kk*8 + tg;
                int cc = warpN + ni*8 + g;
                bf[0] = Bs[rr][cc];
                bf[1] = Bs[rr+4][cc];
#pragma unroll
                for (int mi = 0; mi < 2; mi++)
                    mma_tf32(acc[mi][ni], af[mi], bf);
            }
        }
        __syncthreads();
    }

    // epilogue: each thread owns 2x8 tiles of (2 rows x 2 cols) fragments
#pragma unroll
    for (int mi = 0; mi < 2; mi++) {
#pragma unroll
        for (int ni = 0; ni < 8; ni++) {
            int row = rowBase + warpM + mi*16 + g;
            int col = colBase + warpN + ni*8 + tg*2;
            if (col < N) {
                size_t i0 = (size_t)row*N + col;
                size_t i1 = (size_t)(row+8)*N + col;
                float2 o0 = { acc[mi][ni][0], acc[mi][ni][1] };
                float2 o1 = { acc[mi][ni][2], acc[mi][ni][3] };
                if (Res) {
                    float2 r0 = *(const float2*)&Res[i0];
                    float2 r1 = *(const float2*)&Res[i1];
                    o0.x += r0.x; o0.y += r0.y; o1.x += r1.x; o1.y += r1.y;
                }
                *(float2*)&C[i0] = o0;
                *(float2*)&C[i1] = o1;
            }
        }
    }
}

// ---------------- fp32 SIMT GEMM (kept for tiny-N projections) -------------
__global__ __launch_bounds__(256, 2)
void sgemm_k(const float* __restrict__ A, const float* __restrict__ Bm,
             const float* __restrict__ Res, float* __restrict__ C,
             int M, int N, int K)
{
    const int BM=128, BN=128, BK=16;
    __shared__ float As[BM][BK+1];
    __shared__ float Bs[BK][BN];
    int tid = threadIdx.x;
    int tx = tid & 15, ty = tid >> 4;
    int rowBase = blockIdx.y * BM;
    int colBase = blockIdx.x * BN;

    float acc[8][8];
#pragma unroll
    for (int i=0;i<8;i++)
#pragma unroll
        for (int j=0;j<8;j++) acc[i][j]=0.f;

    for (int k0 = 0; k0 < K; k0 += BK) {
#pragma unroll
        for (int i = tid; i < BM*BK; i += 256) {
            int m = i >> 4, kk = i & 15;
            As[m][kk] = A[(size_t)(rowBase+m)*K + k0 + kk];
        }
#pragma unroll
        for (int i = tid; i < BK*BN; i += 256) {
            int kk = i >> 7, n = i & 127;
            int col = colBase + n;
            Bs[kk][n] = (col < N) ? Bm[(size_t)(k0+kk)*N + col] : 0.f;
        }
        __syncthreads();
#pragma unroll
        for (int kk = 0; kk < BK; kk++) {
            float a_[8];
#pragma unroll
            for (int i=0;i<8;i++) a_[i] = As[ty*8+i][kk];
            float4 b0 = *(const float4*)&Bs[kk][tx*8];
            float4 b1 = *(const float4*)&Bs[kk][tx*8+4];
            float b_[8] = {b0.x,b0.y,b0.z,b0.w,b1.x,b1.y,b1.z,b1.w};
#pragma unroll
            for (int i=0;i<8;i++)
#pragma unroll
                for (int j=0;j<8;j++) acc[i][j] = fmaf(a_[i], b_[j], acc[i][j]);
        }
        __syncthreads();
    }
#pragma unroll
    for (int i=0;i<8;i++) {
        int row = rowBase + ty*8 + i;
#pragma unroll
        for (int j=0;j<8;j++) {
            int col = colBase + tx*8 + j;
            if (col < N) {
                size_t idx = (size_t)row*N + col;
                float r = Res ? Res[idx] : 0.f;
                C[idx] = acc[i][j] + r;
            }
        }
    }
}

// ---------------- causal depthwise conv (K=4) + SiLU ----------------
__global__ void conv_silu_k(const float* __restrict__ in, const float* __restrict__ w,
                            float* __restrict__ out, int C)
{
    size_t total = (size_t)NT * C;
    for (size_t idx = (size_t)blockIdx.x*blockDim.x + threadIdx.x; idx < total;
         idx += (size_t)gridDim.x*blockDim.x) {
        int c = (int)(idx % C);
        size_t bt = idx / C;
        int t = (int)(bt % T_);
        int b = (int)(bt / T_);
        float accv = 0.f;
#pragma unroll
        for (int j = 0; j < CONV_; j++) {
            int tt = t - (CONV_-1) + j;
            if (tt >= 0) accv = fmaf(in[((size_t)b*T_ + tt)*C + c], w[c*CONV_ + j], accv);
        }
        out[idx] = siluf_(accv);
    }
}

// ---------------- l2norm over last dim 64, one warp per (b,t,h) row --------
__global__ void l2norm_k(float* __restrict__ p, int nrows)
{
    int warp = (blockIdx.x * blockDim.x + threadIdx.x) >> 5;
    int lane = threadIdx.x & 31;
    if (warp >= nrows) return;
    float* base = p + (size_t)warp * 64;
    float a = base[lane], b = base[lane+32];
    float ss = a*a + b*b;
#pragma unroll
    for (int off = 16; off; off >>= 1) ss += __shfl_xor_sync(0xffffffffu, ss, off);
    float r = rsqrtf(ss + 1e-6f);
    base[lane] = a*r; base[lane+32] = b*r;
}

// ---------------- beta = sigmoid(hb), g = -exp(A_log)*softplus(ha+dt_bias) --
__global__ void beta_g_k(float* __restrict__ hb, float* __restrict__ ha,
                         const float* __restrict__ dt_bias, const float* __restrict__ A_log)
{
    int i = blockIdx.x*blockDim.x + threadIdx.x;
    if (i >= NT*H_) return;
    int h = i & (H_-1);
    hb[i] = sigmoidf_(hb[i]);
    float x = ha[i] + dt_bias[h];
    float sp = (x > 20.f) ? x : log1pf(expf(x));
    ha[i] = -expf(A_log[h]) * sp;
}

// ---------------- gated delta-rule scan: one CTA per (b,h), 128 threads ----
__global__ __launch_bounds__(128, 1)
void scan_k(const float* __restrict__ qn, const float* __restrict__ kn,
            const float* __restrict__ v,  const float* __restrict__ g,
            const float* __restrict__ beta, float* __restrict__ o)
{
    int b = blockIdx.x / H_;
    int h = blockIdx.x % H_;
    int tid = threadIdx.x;

    const float* qb = qn + (size_t)b*T_*KEY_DIM + h*DK_;
    const float* kb = kn + (size_t)b*T_*KEY_DIM + h*DK_;
    const float* vb = v  + (size_t)b*T_*VAL_DIM + h*DV_;
    const float* gb = g  + (size_t)b*T_*H_ + h;
    const float* bb = beta + (size_t)b*T_*H_ + h;
    float*       ob = o  + (size_t)b*T_*VAL_DIM + h*DV_;

    __shared__ float sk[DK_], sq[DK_], sv[DV_];
    __shared__ float s_scal[2];

    float S[DK_];
#pragma unroll
    for (int j = 0; j < DK_; j++) S[j] = 0.f;

    float rk = 0.f, rq = 0.f, rv, rg = 0.f, rb = 0.f;
    if (tid < DK_) { rk = kb[tid]; rq = qb[tid]; }
    rv = vb[tid];
    if (tid == 0) { rg = gb[0]; rb = bb[0]; }

    for (int t = 0; t < T_; t++) {
        if (tid < DK_) { sk[tid] = rk; sq[tid] = rq; }
        sv[tid] = rv;
        if (tid == 0) { s_scal[0] = expf(rg); s_scal[1] = rb; }
        __syncthreads();

        if (t + 1 < T_) {
            size_t qk_off = (size_t)(t+1)*KEY_DIM;
            if (tid < DK_) { rk = kb[qk_off + tid]; rq = qb[qk_off + tid]; }
            rv = vb[(size_t)(t+1)*VAL_DIM + tid];
            if (tid == 0) { rg = gb[(size_t)(t+1)*H_]; rb = bb[(size_t)(t+1)*H_]; }
        }

        float decay = s_scal[0];
        float bt    = s_scal[1];
        float kv = 0.f;
#pragma unroll
        for (int j = 0; j < DK_; j++) kv = fmaf(sk[j], S[j], kv);
        kv *= decay;
        float u = bt * (sv[tid] - kv);
        float oacc = 0.f;
#pragma unroll
        for (int j = 0; j < DK_; j++) {
            float s = fmaf(sk[j], u, S[j]*decay);
            S[j] = s;
            oacc = fmaf(sq[j], s, oacc);
        }
        ob[(size_t)t*VAL_DIM + tid] = oacc * 0.125f;
        __syncthreads();
    }
}

// ---------------- o = rmsnorm(o, w)*silu(gate), one warp per (b,t,h) row ----
__global__ void onorm_gate_k(float* __restrict__ o, const float* __restrict__ gate,
                             const float* __restrict__ w, int nrows)
{
    int warp = (blockIdx.x * blockDim.x + threadIdx.x) >> 5;
    int lane = threadIdx.x & 31;
    if (warp >= nrows) return;
    float* ob = o + (size_t)warp * DV_;
    const float* gb = gate + (size_t)warp * DV_;
    float x[4];
    float ss = 0.f;
#pragma unroll
    for (int i = 0; i < 4; i++) { x[i] = ob[lane + i*32]; ss += x[i]*x[i]; }
#pragma unroll
    for (int off = 16; off; off >>= 1) ss += __shfl_xor_sync(0xffffffffu, ss, off);
    float scale = rsqrtf(ss * (1.0f/(float)DV_) + 1e-6f);
#pragma unroll
    for (int i = 0; i < 4; i++) {
        int d = lane + i*32;
        ob[d] = x[i]*scale*w[d] * siluf_(gb[d]);
    }
}

// ---------------- SwiGLU activation: mg = silu(mg)*mu ----------------
__global__ void act_mul_k(float* __restrict__ mg, const float* __restrict__ mu)
{
    size_t total = (size_t)NT * INTER_;
    for (size_t i = (size_t)blockIdx.x*blockDim.x + threadIdx.x; i < total;
         i += (size_t)gridDim.x*blockDim.x)
        mg[i] = siluf_(mg[i]) * mu[i];
}

// ---------------- launch ----------------
static inline dim3 gemm_grid(int M, int N) { return dim3((N+127)/128, (M+127)/128); }

extern "C" void kernel_launch(void* const* d_in, const int* in_sizes, int n_in,
                              void* d_out, int out_size)
{
    const float* x       = (const float*)d_in[0];
    const float* norm1_w = (const float*)d_in[1];
    const float* Wq      = (const float*)d_in[2];
    const float* Wk      = (const float*)d_in[3];
    const float* Wv      = (const float*)d_in[4];
    const float* Wb      = (const float*)d_in[5];
    const float* Wa      = (const float*)d_in[6];
    const float* Wg      = (const float*)d_in[7];
    const float* Wo      = (const float*)d_in[8];
    const float* conv_q  = (const float*)d_in[9];
    const float* conv_k  = (const float*)d_in[10];
    const float* conv_v  = (const float*)d_in[11];
    const float* dt_bias = (const float*)d_in[12];
    const float* A_log   = (const float*)d_in[13];
    const float* o_norm_w= (const float*)d_in[14];
    const float* norm2_w = (const float*)d_in[15];
    const float* Wgate   = (const float*)d_in[16];
    const float* Wup     = (const float*)d_in[17];
    const float* Wdown   = (const float*)d_in[18];
    float* out = (float*)d_out;

    float* scr = nullptr;
    cudaGetSymbolAddress((void**)&scr, SCR);
    float* Hbuf = scr + OFF_H;
    float* Q    = scr + OFF_Q;
    float* K    = scr + OFF_K;
    float* V    = scr + OFF_V;
    float* QC   = scr + OFF_QC;
    float* KC   = scr + OFF_KC;
    float* VC   = scr + OFF_VC;
    float* GATE = scr + OFF_GATE;
    float* BETA = scr + OFF_BETA;
    float* G    = scr + OFF_G;
    float* O    = scr + OFF_O;
    float* XMID = scr + OFF_XMID;
    float* H2   = scr + OFF_H2;
    float* MG   = scr + OFF_MG;
    float* MU   = scr + OFF_MU;

    // 1) pre-norm
    rmsnorm_k<<<NT, 256>>>(x, norm1_w, Hbuf);

    // 2) projections (tensor-core tf32 for the big ones)
    mma_gemm_k<<<gemm_grid(NT, KEY_DIM), 256>>>(Hbuf, Wq, nullptr, Q, NT, KEY_DIM, D_);
    mma_gemm_k<<<gemm_grid(NT, KEY_DIM), 256>>>(Hbuf, Wk, nullptr, K, NT, KEY_DIM, D_);
    mma_gemm_k<<<gemm_grid(NT, VAL_DIM), 256>>>(Hbuf, Wv, nullptr, V, NT, VAL_DIM, D_);
    sgemm_k<<<gemm_grid(NT, H_),      256>>>(Hbuf, Wb, nullptr, BETA, NT, H_, D_);
    sgemm_k<<<gemm_grid(NT, H_),      256>>>(Hbuf, Wa, nullptr, G, NT, H_, D_);
    mma_gemm_k<<<gemm_grid(NT, VAL_DIM), 256>>>(Hbuf, Wg, nullptr, GATE, NT, VAL_DIM, D_);

    // 3) conv + silu
    conv_silu_k<<<4096, 256>>>(Q, conv_q, QC, KEY_DIM);
    conv_silu_k<<<4096, 256>>>(K, conv_k, KC, KEY_DIM);
    conv_silu_k<<<8192, 256>>>(V, conv_v, VC, VAL_DIM);

    // 4) l2norm q,k (in-place)
    l2norm_k<<<(NT*H_ + 7)/8, 256>>>(QC, NT*H_);
    l2norm_k<<<(NT*H_ + 7)/8, 256>>>(KC, NT*H_);

    // 5) beta / g (in-place on BETA, G)
    beta_g_k<<<(NT*H_ + 255)/256, 256>>>(BETA, G, dt_bias, A_log);

    // 6) sequential gated delta-rule scan
    scan_k<<<B_*H_, 128>>>(QC, KC, VC, G, BETA, O);

    // 7) gated output norm (in-place on O)
    onorm_gate_k<<<(NT*H_ + 7)/8, 256>>>(O, GATE, o_norm_w, NT*H_);

    // 8) output projection + residual
    mma_gemm_k<<<gemm_grid(NT, D_), 256>>>(O, Wo, x, XMID, NT, D_, VAL_DIM);

    // 9) MLP
    rmsnorm_k<<<NT, 256>>>(XMID, norm2_w, H2);
    mma_gemm_k<<<gemm_grid(NT, INTER_), 256>>>(H2, Wgate, nullptr, MG, NT, INTER_, D_);
    mma_gemm_k<<<gemm_grid(NT, INTER_), 256>>>(H2, Wup,   nullptr, MU, NT, INTER_, D_);
    act_mul_k<<<8192, 256>>>(MG, MU);
    mma_gemm_k<<<gemm_grid(NT, D_), 256>>>(MG, Wdown, XMID, out, NT, D_, INTER_);
}

// round 3
// speedup vs baseline: 2.7065x; 1.3109x over previous
#include <cuda_runtime.h>
#include <math.h>
#include <stdint.h>

// ---------------- problem constants ----------------
#define B_    2
#define T_    2048
#define D_    1024
#define H_    16
#define DK_   64
#define DV_   128
#define NT    (B_*T_)       // 4096 tokens
#define KEY_DIM  1024
#define VAL_DIM  2048
#define INTER_   2752
#define CONV_    4

// ---------------- scratch (static device memory; no allocs allowed) ----------
constexpr size_t OFF_H    = 0;
constexpr size_t OFF_Q    = OFF_H    + (size_t)NT*D_;
constexpr size_t OFF_K    = OFF_Q    + (size_t)NT*KEY_DIM;
constexpr size_t OFF_V    = OFF_K    + (size_t)NT*KEY_DIM;
constexpr size_t OFF_QC   = OFF_V    + (size_t)NT*VAL_DIM;
constexpr size_t OFF_KC   = OFF_QC   + (size_t)NT*KEY_DIM;
constexpr size_t OFF_VC   = OFF_KC   + (size_t)NT*KEY_DIM;
constexpr size_t OFF_GATE = OFF_VC   + (size_t)NT*VAL_DIM;
constexpr size_t OFF_BETA = OFF_GATE + (size_t)NT*VAL_DIM;
constexpr size_t OFF_G    = OFF_BETA + (size_t)NT*H_;
constexpr size_t OFF_O    = OFF_G    + (size_t)NT*H_;
constexpr size_t OFF_XMID = OFF_O    + (size_t)NT*VAL_DIM;
constexpr size_t OFF_H2   = OFF_XMID + (size_t)NT*D_;
constexpr size_t OFF_MG   = OFF_H2   + (size_t)NT*D_;
constexpr size_t OFF_MU   = OFF_MG   + (size_t)NT*INTER_;
constexpr size_t SCR_TOTAL= OFF_MU   + (size_t)NT*INTER_;

__device__ float SCR[SCR_TOTAL];

// ---------------- helpers ----------------
__device__ __forceinline__ float sigmoidf_(float x){ return 1.0f/(1.0f+expf(-x)); }
__device__ __forceinline__ float siluf_(float x){ return x*sigmoidf_(x); }
__device__ __forceinline__ void mma_tf32(float c[4], const uint32_t a[4], const uint32_t b[2]){
    asm volatile(
        "mma.sync.aligned.m16n8k8.row.col.f32.tf32.tf32.f32 "
        "{%0,%1,%2,%3}, {%4,%5,%6,%7}, {%8,%9}, {%0,%1,%2,%3};"
        : "+f"(c[0]), "+f"(c[1]), "+f"(c[2]), "+f"(c[3])
        : "r"(a[0]), "r"(a[1]), "r"(a[2]), "r"(a[3]), "r"(b[0]), "r"(b[1]));
}
__device__ __forceinline__ void cp16(void* dst, const void* src, int bytes){
    uint32_t d = (uint32_t)__cvta_generic_to_shared(dst);
    asm volatile("cp.async.cg.shared.global [%0], [%1], 16, %2;\n" :: "r"(d), "l"(src), "r"(bytes));
}

// ---------------- rmsnorm over D=1024, one block per row ----------------
__global__ void rmsnorm_k(const float* __restrict__ x, const float* __restrict__ w,
                          float* __restrict__ out)
{
    int row = blockIdx.x;
    const float* xr = x + (size_t)row * D_;
    float*       orow = out + (size_t)row * D_;
    int tid = threadIdx.x;
    float v[4];
    float ss = 0.f;
#pragma unroll
    for (int i = 0; i < 4; i++) { v[i] = xr[tid + i*256]; ss += v[i]*v[i]; }
#pragma unroll
    for (int off = 16; off; off >>= 1) ss += __shfl_xor_sync(0xffffffffu, ss, off);
    __shared__ float red[8];
    int wid = tid >> 5, lane = tid & 31;
    if (lane == 0) red[wid] = ss;
    __syncthreads();
    if (wid == 0) {
        float t = (lane < 8) ? red[lane] : 0.f;
#pragma unroll
        for (int off = 4; off; off >>= 1) t += __shfl_xor_sync(0xffffffffu, t, off);
        if (lane == 0) red[0] = t;
    }
    __syncthreads();
    float scale = rsqrtf(red[0] * (1.0f/(float)D_) + 1e-6f);
#pragma unroll
    for (int i = 0; i < 4; i++) orow[tid + i*256] = v[i]*scale*w[tid + i*256];
}

// ---------------- TF32 tensor-core GEMM with cp.async double buffering -----
// C = A[M,K] @ B[K,N] (+Res). 128x128x32 tile, 256 thr, warp tile 32x64.
// M mult of 128, K mult of 32; N guarded (mult of 4 at 16B granularity).
// fp32 bits fed directly to tf32 mma (hardware mantissa truncation).
constexpr int A_PITCH = 36;
constexpr int B_PITCH = 136;
constexpr int SA_ELEM = 128*A_PITCH;             // 4608 floats
constexpr int SB_ELEM = 32*B_PITCH;              // 4352 floats
constexpr int STAGE_ELEM = SA_ELEM + SB_ELEM;    // 8960 floats = 35840 B
constexpr int GEMM_SMEM_BYTES = 2*STAGE_ELEM*4;  // 71680 B

__global__ __launch_bounds__(256)
void mma_gemm_k(const float* __restrict__ A, const float* __restrict__ Bm,
                const float* __restrict__ Res, float* __restrict__ C,
                int M, int N, int K)
{
    extern __shared__ float smem[];
    int tid = threadIdx.x;
    int lane = tid & 31, warp = tid >> 5;
    int warpM = (warp & 3) * 32;
    int warpN = (warp >> 2) * 64;
    int rowBase = blockIdx.y * 128;
    int colBase = blockIdx.x * 128;
    int g = lane >> 2, tg = lane & 3;

    float acc[2][8][4];
#pragma unroll
    for (int mi=0;mi<2;mi++)
#pragma unroll
        for (int ni=0;ni<8;ni++)
#pragma unroll
            for (int j=0;j<4;j++) acc[mi][ni][j] = 0.f;

    // per-thread cp.async mapping: 4 x 16B for A, 4 x 16B for B
    int aRow[4], aCol[4], bRow[4], bCol[4];
#pragma unroll
    for (int p = 0; p < 4; p++) {
        int i = tid + p*256;
        aRow[p] = i >> 3;   aCol[p] = (i & 7) * 4;    // A tile: 128 x 32
        bRow[p] = i >> 5;   bCol[p] = (i & 31) * 4;   // B tile: 32 x 128
    }

    auto issue_stage = [&](int st, int k0){
        float* sa = smem + st*STAGE_ELEM;
        float* sb = sa + SA_ELEM;
#pragma unroll
        for (int p = 0; p < 4; p++) {
            cp16(&sa[aRow[p]*A_PITCH + aCol[p]],
                 &A[(size_t)(rowBase + aRow[p])*K + k0 + aCol[p]], 16);
        }
#pragma unroll
        for (int p = 0; p < 4; p++) {
            int col = colBase + bCol[p];
            int ok = (col < N);
            cp16(&sb[bRow[p]*B_PITCH + bCol[p]],
                 &Bm[(size_t)(k0 + bRow[p])*N + (ok ? col : 0)], ok ? 16 : 0);
        }
        asm volatile("cp.async.commit_group;\n");
    };

    issue_stage(0, 0);
    int st = 0;
    for (int k0 = 0; k0 < K; k0 += 32, st ^= 1) {
        if (k0 + 32 < K) {
            issue_stage(st ^ 1, k0 + 32);
            asm volatile("cp.async.wait_group 1;\n");
        } else {
            asm volatile("cp.async.wait_group 0;\n");
        }
        __syncthreads();

        const float* sa = smem + st*STAGE_ELEM;
        const float* sb = sa + SA_ELEM;
#pragma unroll
        for (int kk = 0; kk < 4; kk++) {
            uint32_t af[2][4];
#pragma unroll
            for (int mi = 0; mi < 2; mi++) {
                int r = warpM + mi*16 + g;
                int c = kk*8 + tg;
                af[mi][0] = __float_as_uint(sa[r*A_PITCH + c]);
                af[mi][1] = __float_as_uint(sa[(r+8)*A_PITCH + c]);
                af[mi][2] = __float_as_uint(sa[r*A_PITCH + c+4]);
                af[mi][3] = __float_as_uint(sa[(r+8)*A_PITCH + c+4]);
            }
#pragma unroll
            for (int ni = 0; ni < 8; ni++) {
                int rr = kk*8 + tg;
                int cc = warpN + ni*8 + g;
                uint32_t bf[2];
                bf[0] = __float_as_uint(sb[rr*B_PITCH + cc]);
                bf[1] = __float_as_uint(sb[(rr+4)*B_PITCH + cc]);
#pragma unroll
                for (int mi = 0; mi < 2; mi++)
                    mma_tf32(acc[mi][ni], af[mi], bf);
            }
        }
        __syncthreads();   // stage st may be refilled next iteration
    }

    // epilogue
#pragma unroll
    for (int mi = 0; mi < 2; mi++) {
#pragma unroll
        for (int ni = 0; ni < 8; ni++) {
            int row = rowBase + warpM + mi*16 + g;
            int col = colBase + warpN + ni*8 + tg*2;
            if (col < N) {
                size_t i0 = (size_t)row*N + col;
                size_t i1 = (size_t)(row+8)*N + col;
                float2 o0 = { acc[mi][ni][0], acc[mi][ni][1] };
                float2 o1 = { acc[mi][ni][2], acc[mi][ni][3] };
                if (Res) {
                    float2 r0 = *(const float2*)&Res[i0];
                    float2 r1 = *(const float2*)&Res[i1];
                    o0.x += r0.x; o0.y += r0.y; o1.x += r1.x; o1.y += r1.y;
                }
                *(float2*)&C[i0] = o0;
                *(float2*)&C[i1] = o1;
            }
        }
    }
}

// ---------------- fused beta/g: warp per token, 32 dots of K=1024 ----------
__global__ void betag_k(const float* __restrict__ Hb, const float* __restrict__ Wb,
                        const float* __restrict__ Wa, const float* __restrict__ dtb,
                        const float* __restrict__ Alog,
                        float* __restrict__ BETA, float* __restrict__ G)
{
    int warp = (blockIdx.x * blockDim.x + threadIdx.x) >> 5;
    int lane = threadIdx.x & 31;
    if (warp >= NT) return;
    const float* hr = Hb + (size_t)warp * D_;
    int col = lane & 15;
    const float* W = (lane < 16) ? Wb : Wa;
    float acc = 0.f;
    for (int d0 = 0; d0 < D_; d0 += 32) {
        float hv = hr[d0 + lane];
#pragma unroll
        for (int j = 0; j < 32; j++) {
            float hd = __shfl_sync(0xffffffffu, hv, j);
            acc = fmaf(hd, W[(size_t)(d0 + j)*H_ + col], acc);
        }
    }
    if (lane < 16) {
        BETA[(size_t)warp*H_ + col] = sigmoidf_(acc);
    } else {
        float xx = acc + dtb[col];
        float sp = (xx > 20.f) ? xx : log1pf(expf(xx));
        G[(size_t)warp*H_ + col] = -expf(Alog[col]) * sp;
    }
}

// ---------------- causal depthwise conv (K=4) + SiLU ----------------
__global__ void conv_silu_k(const float* __restrict__ in, const float* __restrict__ w,
                            float* __restrict__ out, int C)
{
    size_t total = (size_t)NT * C;
    for (size_t idx = (size_t)blockIdx.x*blockDim.x + threadIdx.x; idx < total;
         idx += (size_t)gridDim.x*blockDim.x) {
        int c = (int)(idx % C);
        size_t bt = idx / C;
        int t = (int)(bt % T_);
        int b = (int)(bt / T_);
        float accv = 0.f;
#pragma unroll
        for (int j = 0; j < CONV_; j++) {
            int tt = t - (CONV_-1) + j;
            if (tt >= 0) accv = fmaf(in[((size_t)b*T_ + tt)*C + c], w[c*CONV_ + j], accv);
        }
        out[idx] = siluf_(accv);
    }
}

// ---------------- l2norm over last dim 64, one warp per (b,t,h) row --------
__global__ void l2norm_k(float* __restrict__ p, int nrows)
{
    int warp = (blockIdx.x * blockDim.x + threadIdx.x) >> 5;
    int lane = threadIdx.x & 31;
    if (warp >= nrows) return;
    float* base = p + (size_t)warp * 64;
    float a = base[lane], b = base[lane+32];
    float ss = a*a + b*b;
#pragma unroll
    for (int off = 16; off; off >>= 1) ss += __shfl_xor_sync(0xffffffffu, ss, off);
    float r = rsqrtf(ss + 1e-6f);
    base[lane] = a*r; base[lane+32] = b*r;
}

// ---------------- gated delta-rule scan ----------------
// 4 CTAs per (b,h) over v-chunks of 32; 256 threads: v-local = tid>>3 (32),
// k-split = tid&7 (8 k's each, S[8] per thread). 3-level shfl reductions.
__global__ __launch_bounds__(256, 1)
void scan_k(const float* __restrict__ qn, const float* __restrict__ kn,
            const float* __restrict__ v,  const float* __restrict__ g,
            const float* __restrict__ beta, float* __restrict__ o)
{
    int cta = blockIdx.x;         // 0..127
    int vchunk = cta & 3;
    int bh = cta >> 2;
    int b = bh >> 4, h = bh & 15;
    int tid = threadIdx.x;
    int vloc = tid >> 3, kq = tid & 7;

    const float* qb = qn + (size_t)b*T_*KEY_DIM + h*DK_;
    const float* kb = kn + (size_t)b*T_*KEY_DIM + h*DK_;
    const float* vb = v  + (size_t)b*T_*VAL_DIM + h*DV_ + vchunk*32;
    const float* gb = g  + (size_t)b*T_*H_ + h;
    const float* bb = beta + (size_t)b*T_*H_ + h;
    float*       ob = o  + (size_t)b*T_*VAL_DIM + h*DV_ + vchunk*32;

    __shared__ float sk[DK_], sq[DK_], sv[32];
    __shared__ float s_scal[2];

    float S[8];
#pragma unroll
    for (int j = 0; j < 8; j++) S[j] = 0.f;

    // prefetch t=0
    float rk = 0.f, rq = 0.f, rv = 0.f, rg = 0.f, rb = 0.f;
    if (tid < 64)       { rk = kb[tid]; rq = qb[tid]; }
    else if (tid < 96)  { rv = vb[tid - 64]; }
    if (tid == 0)       { rg = gb[0]; rb = bb[0]; }

    for (int t = 0; t < T_; t++) {
        if (tid < 64)       { sk[tid] = rk; sq[tid] = rq; }
        else if (tid < 96)  { sv[tid - 64] = rv; }
        if (tid == 0)       { s_scal[0] = expf(rg); s_scal[1] = rb; }
        __syncthreads();

        if (t + 1 < T_) {
            if (tid < 64) {
                size_t off = (size_t)(t+1)*KEY_DIM;
                rk = kb[off + tid]; rq = qb[off + tid];
            } else if (tid < 96) {
                rv = vb[(size_t)(t+1)*VAL_DIM + (tid - 64)];
            }
            if (tid == 0) { rg = gb[(size_t)(t+1)*H_]; rb = bb[(size_t)(t+1)*H_]; }
        }

        float decay = s_scal[0];
        float bt    = s_scal[1];
        const float* skp = sk + kq*8;
        const float* sqp = sq + kq*8;

        float kv = 0.f;
#pragma unroll
        for (int j = 0; j < 8; j++) kv = fmaf(skp[j], S[j], kv);
        kv += __shfl_xor_sync(0xffffffffu, kv, 1);
        kv += __shfl_xor_sync(0xffffffffu, kv, 2);
        kv += __shfl_xor_sync(0xffffffffu, kv, 4);
        kv *= decay;

        float u = bt * (sv[vloc] - kv);
        float oacc = 0.f;
#pragma unroll
        for (int j = 0; j < 8; j++) {
            float s = fmaf(skp[j], u, S[j]*decay);
            S[j] = s;
            oacc = fmaf(sqp[j], s, oacc);
        }
        oacc += __shfl_xor_sync(0xffffffffu, oacc, 1);
        oacc += __shfl_xor_sync(0xffffffffu, oacc, 2);
        oacc += __shfl_xor_sync(0xffffffffu, oacc, 4);
        if (kq == 0) ob[(size_t)t*VAL_DIM + vloc] = oacc * 0.125f;
        __syncthreads();
    }
}

// ---------------- o = rmsnorm(o, w)*silu(gate), one warp per (b,t,h) row ----
__global__ void onorm_gate_k(float* __restrict__ o, const float* __restrict__ gate,
                             const float* __restrict__ w, int nrows)
{
    int warp = (blockIdx.x * blockDim.x + threadIdx.x) >> 5;
    int lane = threadIdx.x & 31;
    if (warp >= nrows) return;
    float* ob = o + (size_t)warp * DV_;
    const float* gb = gate + (size_t)warp * DV_;
    float x[4];
    float ss = 0.f;
#pragma unroll
    for (int i = 0; i < 4; i++) { x[i] = ob[lane + i*32]; ss += x[i]*x[i]; }
#pragma unroll
    for (int off = 16; off; off >>= 1) ss += __shfl_xor_sync(0xffffffffu, ss, off);
    float scale = rsqrtf(ss * (1.0f/(float)DV_) + 1e-6f);
#pragma unroll
    for (int i = 0; i < 4; i++) {
        int d = lane + i*32;
        ob[d] = x[i]*scale*w[d] * siluf_(gb[d]);
    }
}

// ---------------- SwiGLU activation: mg = silu(mg)*mu ----------------
__global__ void act_mul_k(float* __restrict__ mg, const float* __restrict__ mu)
{
    size_t total = (size_t)NT * INTER_;
    for (size_t i = (size_t)blockIdx.x*blockDim.x + threadIdx.x; i < total;
         i += (size_t)gridDim.x*blockDim.x)
        mg[i] = siluf_(mg[i]) * mu[i];
}

// ---------------- launch ----------------
static inline dim3 gemm_grid(int M, int N) { return dim3((N+127)/128, (M+127)/128); }

extern "C" void kernel_launch(void* const* d_in, const int* in_sizes, int n_in,
                              void* d_out, int out_size)
{
    const float* x       = (const float*)d_in[0];
    const float* norm1_w = (const float*)d_in[1];
    const float* Wq      = (const float*)d_in[2];
    const float* Wk      = (const float*)d_in[3];
    const float* Wv      = (const float*)d_in[4];
    const float* Wb      = (const float*)d_in[5];
    const float* Wa      = (const float*)d_in[6];
    const float* Wg      = (const float*)d_in[7];
    const float* Wo      = (const float*)d_in[8];
    const float* conv_q  = (const float*)d_in[9];
    const float* conv_k  = (const float*)d_in[10];
    const float* conv_v  = (const float*)d_in[11];
    const float* dt_bias = (const float*)d_in[12];
    const float* A_log   = (const float*)d_in[13];
    const float* o_norm_w= (const float*)d_in[14];
    const float* norm2_w = (const float*)d_in[15];
    const float* Wgate   = (const float*)d_in[16];
    const float* Wup     = (const float*)d_in[17];
    const float* Wdown   = (const float*)d_in[18];
    float* out = (float*)d_out;

    float* scr = nullptr;
    cudaGetSymbolAddress((void**)&scr, SCR);
    float* Hbuf = scr + OFF_H;
    float* Q    = scr + OFF_Q;
    float* K    = scr + OFF_K;
    float* V    = scr + OFF_V;
    float* QC   = scr + OFF_QC;
    float* KC   = scr + OFF_KC;
    float* VC   = scr + OFF_VC;
    float* GATE = scr + OFF_GATE;
    float* BETA = scr + OFF_BETA;
    float* G    = scr + OFF_G;
    float* O    = scr + OFF_O;
    float* XMID = scr + OFF_XMID;
    float* H2   = scr + OFF_H2;
    float* MG   = scr + OFF_MG;
    float* MU   = scr + OFF_MU;

    cudaFuncSetAttribute(mma_gemm_k, cudaFuncAttributeMaxDynamicSharedMemorySize,
                         GEMM_SMEM_BYTES);

    // 1) pre-norm
    rmsnorm_k<<<NT, 256>>>(x, norm1_w, Hbuf);

    // 2) projections
    mma_gemm_k<<<gemm_grid(NT, KEY_DIM), 256, GEMM_SMEM_BYTES>>>(Hbuf, Wq, nullptr, Q, NT, KEY_DIM, D_);
    mma_gemm_k<<<gemm_grid(NT, KEY_DIM), 256, GEMM_SMEM_BYTES>>>(Hbuf, Wk, nullptr, K, NT, KEY_DIM, D_);
    mma_gemm_k<<<gemm_grid(NT, VAL_DIM), 256, GEMM_SMEM_BYTES>>>(Hbuf, Wv, nullptr, V, NT, VAL_DIM, D_);
    mma_gemm_k<<<gemm_grid(NT, VAL_DIM), 256, GEMM_SMEM_BYTES>>>(Hbuf, Wg, nullptr, GATE, NT, VAL_DIM, D_);
    betag_k<<<(NT*32 + 255)/256, 256>>>(Hbuf, Wb, Wa, dt_bias, A_log, BETA, G);

    // 3) conv + silu
    conv_silu_k<<<4096, 256>>>(Q, conv_q, QC, KEY_DIM);
    conv_silu_k<<<4096, 256>>>(K, conv_k, KC, KEY_DIM);
    conv_silu_k<<<8192, 256>>>(V, conv_v, VC, VAL_DIM);

    // 4) l2norm q,k (in-place)
    l2norm_k<<<(NT*H_ + 7)/8, 256>>>(QC, NT*H_);
    l2norm_k<<<(NT*H_ + 7)/8, 256>>>(KC, NT*H_);

    // 5) sequential gated delta-rule scan (128 CTAs)
    scan_k<<<B_*H_*4, 256>>>(QC, KC, VC, G, BETA, O);

    // 6) gated output norm (in-place on O)
    onorm_gate_k<<<(NT*H_ + 7)/8, 256>>>(O, GATE, o_norm_w, NT*H_);

    // 7) output projection + residual
    mma_gemm_k<<<gemm_grid(NT, D_), 256, GEMM_SMEM_BYTES>>>(O, Wo, x, XMID, NT, D_, VAL_DIM);

    // 8) MLP
    rmsnorm_k<<<NT, 256>>>(XMID, norm2_w, H2);
    mma_gemm_k<<<gemm_grid(NT, INTER_), 256, GEMM_SMEM_BYTES>>>(H2, Wgate, nullptr, MG, NT, INTER_, D_);
    mma_gemm_k<<<gemm_grid(NT, INTER_), 256, GEMM_SMEM_BYTES>>>(H2, Wup,   nullptr, MU, NT, INTER_, D_);
    act_mul_k<<<8192, 256>>>(MG, MU);
    mma_gemm_k<<<gemm_grid(NT, D_), 256, GEMM_SMEM_BYTES>>>(MG, Wdown, XMID, out, NT, D_, INTER_);
}